// round 11
// baseline (speedup 1.0000x reference)
#include <cuda_runtime.h>
#include <cuda_bf16.h>
#include <cstdint>

#define C_DIM  64
#define TILE_P 64

// M fragments pre-packed in per-lane mma order: index ((gblk*4+k)*4+j)*32+lane
__device__ uint32_t g_Ahi[4 * 4 * 4 * 32];
__device__ uint32_t g_Alo[4 * 4 * 4 * 32];

__device__ __forceinline__ uint32_t pack_bf16(float lo, float hi) {
    uint32_t r;
    asm("cvt.rn.bf16x2.f32 %0, %1, %2;" : "=r"(r) : "f"(hi), "f"(lo));
    return r;
}
__device__ __forceinline__ float lo_f32(uint32_t p) { return __uint_as_float(p << 16); }
__device__ __forceinline__ float hi_f32(uint32_t p) { return __uint_as_float(p & 0xFFFF0000u); }

#define MMA(d, A, b0, b1)                                                     \
    asm volatile("mma.sync.aligned.m16n8k16.row.col.f32.bf16.bf16.f32 "       \
                 "{%0,%1,%2,%3}, {%4,%5,%6,%7}, {%8,%9}, {%0,%1,%2,%3};"      \
                 : "+f"((d)[0]), "+f"((d)[1]), "+f"((d)[2]), "+f"((d)[3])     \
                 : "r"((A)[0]), "r"((A)[1]), "r"((A)[2]), "r"((A)[3]),        \
                   "r"(b0), "r"(b1))

// ---------------------------------------------------------------------------
// Kernel A: M = Qinv * diag(exp(T*(-2*|S|))) * Q, emitted directly as bf16
// hi/lo mma A-fragments. grid 8 x 256; thread t computes M[g][c], M[g][c+1].
// ---------------------------------------------------------------------------
__global__ void build_M_kernel(const float* __restrict__ S,
                               const float* __restrict__ Q,
                               const float* __restrict__ Qinv,
                               const int* __restrict__ T) {
    __shared__ float sQ[C_DIM * C_DIM];
    __shared__ float sQi[C_DIM * C_DIM];
    __shared__ float se[C_DIM];
    int tid = threadIdx.x;
    for (int i = tid; i < C_DIM * C_DIM; i += blockDim.x) {
        sQ[i]  = Q[i];
        sQi[i] = Qinv[i];
    }
    if (tid < C_DIM) {
        float t_total = (float)(*T);
        se[tid] = expf(t_total * (-2.0f * fabsf(S[tid])));
    }
    __syncthreads();

    int t = blockIdx.x * blockDim.x + tid;   // 0..2047
    int g = t >> 5;
    int c = (t & 31) * 2;
    float a0 = 0.0f, a1 = 0.0f;
    #pragma unroll
    for (int f = 0; f < C_DIM; f++) {
        float w = sQi[g * C_DIM + f] * se[f];
        a0 += w * sQ[f * C_DIM + c];
        a1 += w * sQ[f * C_DIM + c + 1];
    }
    uint32_t h = pack_bf16(a0, a1);
    uint32_t l = pack_bf16(a0 - lo_f32(h), a1 - hi_f32(h));

    int gblk = g >> 4;
    int gg   = g & 15;
    int gid  = gg & 7;
    int half = gg >> 3;
    int k    = c >> 4;
    int cc   = c & 15;
    int tig  = (cc >> 1) & 3;
    int j    = ((cc >> 3) << 1) + half;
    int lane = gid * 4 + tig;
    int off  = (((gblk * 4) + k) * 4 + j) * 32 + lane;
    g_Ahi[off] = h;
    g_Alo[off] = l;
}

// ---------------------------------------------------------------------------
// Kernel B: barrier-free streaming GEMM. 128 thr = 4 warps, each warp owns
// 32 g-rows x 32 pixels. B operands loaded DIRECTLY from global (each LDG.32
// is 4 rows x 8 consecutive px = 4 full sectors, perfectly coalesced), split
// to bf16 hi/lo in registers, 3 MMAs per fragment pair. No smem, no syncs.
// ---------------------------------------------------------------------------
__global__ __launch_bounds__(128, 4)
void apply_mma_kernel(const float* __restrict__ x,
                      float* __restrict__ out, int HW) {
    int tid   = threadIdx.x;
    int wid   = tid >> 5;
    int lane  = tid & 31;
    int gid   = lane >> 2;
    int tig   = lane & 3;
    int gpair = wid & 1;        // g half (32 rows)
    int pq    = wid >> 1;       // pixel half of the 64-px tile (32 px)

    // ---- A fragments: 2 quadrants x 4 k x 4 j, hi+lo (64 regs) ----
    uint32_t Ahi[2][4][4], Alo[2][4][4];
    #pragma unroll
    for (int q = 0; q < 2; q++)
        #pragma unroll
        for (int k = 0; k < 4; k++)
            #pragma unroll
            for (int j = 0; j < 4; j++) {
                int off = (((gpair * 2 + q) * 4 + k) * 4 + j) * 32 + lane;
                Ahi[q][k][j] = g_Ahi[off];
                Alo[q][k][j] = g_Alo[off];
            }

    // ---- CTA coords: 64 consecutive pixels (never crosses batch) ----
    int Q0 = blockIdx.x * TILE_P;
    int b  = Q0 / HW;
    int p0 = Q0 - b * HW;
    const float* xb = x   + (size_t)b * C_DIM * HW + p0;
    float*       ob = out + (size_t)b * C_DIM * HW + p0;

    // per-thread B base: row = tig*2, px = pq*32 + gid
    const float* xt = xb + (size_t)(tig * 2) * HW + pq * 32 + gid;

    float d[2][4][4];
    #pragma unroll
    for (int q = 0; q < 2; q++)
        #pragma unroll
        for (int nt = 0; nt < 4; nt++)
            #pragma unroll
            for (int j = 0; j < 4; j++) d[q][nt][j] = 0.0f;

    #pragma unroll
    for (int k = 0; k < 4; k++) {
        const float* xk = xt + (size_t)(k * 16) * HW;
        // load all 16 values for this k (16 independent LDGs in flight)
        float f[4][4];
        #pragma unroll
        for (int nt = 0; nt < 4; nt++) {
            const float* p = xk + nt * 8;
            f[nt][0] = __ldg(p);
            f[nt][1] = __ldg(p + (size_t)HW);
            f[nt][2] = __ldg(p + (size_t)8 * HW);
            f[nt][3] = __ldg(p + (size_t)9 * HW);
        }
        #pragma unroll
        for (int nt = 0; nt < 4; nt++) {
            uint32_t h0 = pack_bf16(f[nt][0], f[nt][1]);
            uint32_t h1 = pack_bf16(f[nt][2], f[nt][3]);
            uint32_t l0 = pack_bf16(f[nt][0] - lo_f32(h0), f[nt][1] - hi_f32(h0));
            uint32_t l1 = pack_bf16(f[nt][2] - lo_f32(h1), f[nt][3] - hi_f32(h1));
            MMA(d[0][nt], Ahi[0][k], h0, h1);
            MMA(d[0][nt], Alo[0][k], h0, h1);
            MMA(d[0][nt], Ahi[0][k], l0, l1);
            MMA(d[1][nt], Ahi[1][k], h0, h1);
            MMA(d[1][nt], Alo[1][k], h0, h1);
            MMA(d[1][nt], Ahi[1][k], l0, l1);
        }
    }

    // ---- epilogue: coalesced float2 stores ----
    #pragma unroll
    for (int q = 0; q < 2; q++) {
        int r0 = gpair * 32 + q * 16 + gid;
        float* o0 = ob + (size_t)r0 * HW + pq * 32;
        float* o1 = o0 + (size_t)8 * HW;
        #pragma unroll
        for (int nt = 0; nt < 4; nt++) {
            int p = nt * 8 + tig * 2;
            float2 v0; v0.x = d[q][nt][0]; v0.y = d[q][nt][1];
            float2 v1; v1.x = d[q][nt][2]; v1.y = d[q][nt][3];
            *(float2*)(o0 + p) = v0;
            *(float2*)(o1 + p) = v1;
        }
    }
}

// ---------------------------------------------------------------------------
// Inputs: x [4,64,512,512] f32, S [64] f32, Q [64,64] f32, Qinv [64,64] f32,
// T [] int32. Output: f32 same shape as x.
// ---------------------------------------------------------------------------
extern "C" void kernel_launch(void* const* d_in, const int* in_sizes, int n_in,
                              void* d_out, int out_size) {
    const float* x   = (const float*)d_in[0];
    const float* S   = (const float*)d_in[1];
    const float* Q   = (const float*)d_in[2];
    const float* Qi  = (const float*)d_in[3];
    const int*   T   = (const int*)d_in[4];
    float*       out = (float*)d_out;

    int Npix = in_sizes[0] / C_DIM;   // B*H*W = 1,048,576
    int HW   = Npix / 4;              // B = 4

    build_M_kernel<<<8, 256>>>(S, Q, Qi, T);
    int grid = Npix / TILE_P;         // 16384
    apply_mma_kernel<<<grid, 128>>>(x, out, HW);
}

// round 12
// speedup vs baseline: 1.3231x; 1.3231x over previous
#include <cuda_runtime.h>
#include <cuda_fp16.h>
#include <cstdint>

#define C_DIM   64
#define TILE_P  128
#define TILES   4
#define STRIDE  132                       // floats per c-row (528B): conflict-free
#define BUF_FLOATS (C_DIM * STRIDE)       // 8448 floats = 33792 B per buffer
#define SMEM_BYTES (2 * BUF_FLOATS * 4)   // 67584 B

// M fragments (fp16 pairs) pre-packed in per-lane mma order:
// index ((gblk*4+k)*4+j)*32+lane
__device__ uint32_t g_Ah[4 * 4 * 4 * 32];

__device__ __forceinline__ uint32_t pack_f16(float lo, float hi) {
    uint32_t r;
    asm("cvt.rn.f16x2.f32 %0, %1, %2;" : "=r"(r) : "f"(hi), "f"(lo));
    return r;
}

#define MMA(d, A, b0, b1)                                                     \
    asm volatile("mma.sync.aligned.m16n8k16.row.col.f32.f16.f16.f32 "         \
                 "{%0,%1,%2,%3}, {%4,%5,%6,%7}, {%8,%9}, {%0,%1,%2,%3};"      \
                 : "+f"((d)[0]), "+f"((d)[1]), "+f"((d)[2]), "+f"((d)[3])     \
                 : "r"((A)[0]), "r"((A)[1]), "r"((A)[2]), "r"((A)[3]),        \
                   "r"(b0), "r"(b1))

#define CP_ASYNC16(sa, ga) \
    asm volatile("cp.async.cg.shared.global [%0], [%1], 16;" :: "r"(sa), "l"(ga))

// ---------------------------------------------------------------------------
// Kernel A: M = Qinv * diag(exp(T*(-2*|S|))) * Q, emitted directly as fp16
// mma A-fragments. grid 8 x 256; thread t computes M[g][c], M[g][c+1].
// ---------------------------------------------------------------------------
__global__ void build_M_kernel(const float* __restrict__ S,
                               const float* __restrict__ Q,
                               const float* __restrict__ Qinv,
                               const int* __restrict__ T) {
    __shared__ float sQ[C_DIM * C_DIM];
    __shared__ float sQi[C_DIM * C_DIM];
    __shared__ float se[C_DIM];
    int tid = threadIdx.x;
    for (int i = tid; i < C_DIM * C_DIM; i += blockDim.x) {
        sQ[i]  = Q[i];
        sQi[i] = Qinv[i];
    }
    if (tid < C_DIM) {
        float t_total = (float)(*T);
        se[tid] = expf(t_total * (-2.0f * fabsf(S[tid])));
    }
    __syncthreads();

    int t = blockIdx.x * blockDim.x + tid;   // 0..2047
    int g = t >> 5;
    int c = (t & 31) * 2;
    float a0 = 0.0f, a1 = 0.0f;
    #pragma unroll
    for (int f = 0; f < C_DIM; f++) {
        float w = sQi[g * C_DIM + f] * se[f];
        a0 += w * sQ[f * C_DIM + c];
        a1 += w * sQ[f * C_DIM + c + 1];
    }
    uint32_t h = pack_f16(a0, a1);

    int gblk = g >> 4;
    int gg   = g & 15;
    int gid  = gg & 7;
    int half = gg >> 3;
    int k    = c >> 4;
    int cc   = c & 15;
    int tig  = (cc >> 1) & 3;
    int j    = ((cc >> 3) << 1) + half;
    int lane = gid * 4 + tig;
    int off  = (((gblk * 4) + k) * 4 + j) * 32 + lane;
    g_Ah[off] = h;
}

// ---------------------------------------------------------------------------
// Kernel B: 256 thr, 4 tiles of 128 px (R7 schedule). Warp = (gpair: 32 g) x
// (pq: 32 px). Raw f32 x tiles stream via whole-tile cp.async double buffer;
// consumers do conflict-free LDS.32 and split to fp16 hi/lo in registers.
// D = Mh*(Xh + Xl): 4 MMAs per (k,nt). 3 CTAs/SM via launch bounds.
// ---------------------------------------------------------------------------
__global__ __launch_bounds__(256, 3)
void apply_mma_kernel(const float* __restrict__ x,
                      float* __restrict__ out, int HW) {
    extern __shared__ __align__(16) float sRaw[];   // 2 x [64][STRIDE]

    int tid   = threadIdx.x;
    int wid   = tid >> 5;
    int lane  = tid & 31;
    int gid   = lane >> 2;
    int tig   = lane & 3;
    int gpair = wid & 1;        // g half (32 rows)
    int pq    = wid >> 1;       // pixel quarter (32 px)

    // ---- A fragments: 2 quadrants x 4 k x 4 j, fp16 hi only (32 regs) ----
    uint32_t Ah[2][4][4];
    #pragma unroll
    for (int q = 0; q < 2; q++)
        #pragma unroll
        for (int k = 0; k < 4; k++)
            #pragma unroll
            for (int j = 0; j < 4; j++) {
                int off = (((gpair * 2 + q) * 4 + k) * 4 + j) * 32 + lane;
                Ah[q][k][j] = g_Ah[off];
            }

    // ---- CTA coords: 512 consecutive pixels (never crosses batch) ----
    int Q0 = blockIdx.x * (TILE_P * TILES);
    int b  = Q0 / HW;
    int p0 = Q0 - b * HW;
    const float* xb = x   + (size_t)b * C_DIM * HW + p0;
    float*       ob = out + (size_t)b * C_DIM * HW + p0;

    uint32_t sb = (uint32_t)__cvta_generic_to_shared(sRaw);
    int prow = tid >> 5;            // producer row base 0..7
    int pcol = (tid & 31) * 4;      // float col (16B segment)

    // issue whole tile t into buffer t&1 (8 x 16B per thread, 1 commit)
    #define ISSUE_TILE(t)                                                      \
        do {                                                                   \
            uint32_t sbase = sb + (((t) & 1) * BUF_FLOATS) * 4;                \
            const float* gbase = xb + (t) * TILE_P + pcol;                     \
            _Pragma("unroll")                                                  \
            for (int i = 0; i < 8; i++) {                                      \
                int row = i * 8 + prow;                                        \
                CP_ASYNC16(sbase + (uint32_t)(row * STRIDE + pcol) * 4,        \
                           gbase + (size_t)row * HW);                          \
            }                                                                  \
            asm volatile("cp.async.commit_group;" ::: "memory");               \
        } while (0)

    ISSUE_TILE(0);

    float d[2][4][4];
    #pragma unroll
    for (int q = 0; q < 2; q++)
        #pragma unroll
        for (int nt = 0; nt < 4; nt++)
            #pragma unroll
            for (int j = 0; j < 4; j++) d[q][nt][j] = 0.0f;

    #pragma unroll 1
    for (int t = 0; t < TILES; t++) {
        asm volatile("cp.async.wait_group 0;" ::: "memory");
        __syncthreads();
        if (t + 1 < TILES) ISSUE_TILE(t + 1);

        const float* sf = sRaw + (t & 1) * BUF_FLOATS;
        #pragma unroll
        for (int k = 0; k < 4; k++) {
            #pragma unroll
            for (int nt = 0; nt < 4; nt++) {
                int p  = pq * 32 + nt * 8 + gid;
                int c0 = k * 16 + tig * 2;
                float f0 = sf[(c0)     * STRIDE + p];
                float f1 = sf[(c0 + 1) * STRIDE + p];
                float f2 = sf[(c0 + 8) * STRIDE + p];
                float f3 = sf[(c0 + 9) * STRIDE + p];
                uint32_t h0 = pack_f16(f0, f1);
                uint32_t h1 = pack_f16(f2, f3);
                float2 b0 = __half22float2(*(__half2*)&h0);
                float2 b1 = __half22float2(*(__half2*)&h1);
                uint32_t l0 = pack_f16(f0 - b0.x, f1 - b0.y);
                uint32_t l1 = pack_f16(f2 - b1.x, f3 - b1.y);
                MMA(d[0][nt], Ah[0][k], h0, h1);
                MMA(d[0][nt], Ah[0][k], l0, l1);
                MMA(d[1][nt], Ah[1][k], h0, h1);
                MMA(d[1][nt], Ah[1][k], l0, l1);
            }
        }

        // ---- epilogue tile t: coalesced float2 stores, reset acc ----
        #pragma unroll
        for (int q = 0; q < 2; q++) {
            int r0 = gpair * 32 + q * 16 + gid;
            float* o0 = ob + (size_t)r0 * HW + t * TILE_P + pq * 32;
            float* o1 = o0 + (size_t)8 * HW;
            #pragma unroll
            for (int nt = 0; nt < 4; nt++) {
                int p = nt * 8 + tig * 2;
                float2 v0; v0.x = d[q][nt][0]; v0.y = d[q][nt][1];
                float2 v1; v1.x = d[q][nt][2]; v1.y = d[q][nt][3];
                *(float2*)(o0 + p) = v0;
                *(float2*)(o1 + p) = v1;
                d[q][nt][0] = 0.0f; d[q][nt][1] = 0.0f;
                d[q][nt][2] = 0.0f; d[q][nt][3] = 0.0f;
            }
        }
    }
}

// ---------------------------------------------------------------------------
// Inputs: x [4,64,512,512] f32, S [64] f32, Q [64,64] f32, Qinv [64,64] f32,
// T [] int32. Output: f32 same shape as x.
// ---------------------------------------------------------------------------
extern "C" void kernel_launch(void* const* d_in, const int* in_sizes, int n_in,
                              void* d_out, int out_size) {
    const float* x   = (const float*)d_in[0];
    const float* S   = (const float*)d_in[1];
    const float* Q   = (const float*)d_in[2];
    const float* Qi  = (const float*)d_in[3];
    const int*   T   = (const int*)d_in[4];
    float*       out = (float*)d_out;

    int Npix = in_sizes[0] / C_DIM;   // B*H*W = 1,048,576
    int HW   = Npix / 4;              // B = 4

    cudaFuncSetAttribute(apply_mma_kernel,
                         cudaFuncAttributeMaxDynamicSharedMemorySize, SMEM_BYTES);

    build_M_kernel<<<8, 256>>>(S, Q, Qi, T);
    int grid = Npix / (TILE_P * TILES);   // 2048
    apply_mma_kernel<<<grid, 256, SMEM_BYTES>>>(x, out, HW);
}